// round 4
// baseline (speedup 1.0000x reference)
#include <cuda_runtime.h>

#define SDIM    7
#define NCELL   49
#define BATCH   16384
#define DSTRIDE 30
#define NPAIR   (BATCH * NCELL)     // 802816
#define NCLASS  20

#define K1_BLOCKS  588
#define K1_THREADS 256
#define K1_STRIDE  (K1_BLOCKS * K1_THREADS)   // 150528 = 49*3072

__device__ float g_has[NPAIR];           // has[b*49+cell], 3.2 MB
__device__ float g_cellsums[3 * NCELL];  // [0..48]=XW, [49..97]=CM, [98..146]=CLS

// Robustly decode a scalar dimension that may be int32/int64/fp32/fp64.
__device__ __forceinline__ float decode_dim(const void* p) {
    if (p == nullptr) return 448.0f;
    int v = *(const int*)p;                       // int32 / low word of int64
    if (v > 0 && v < (1 << 24)) return (float)v;
    float f = __int_as_float(v);                  // fp32
    if (f > 0.0f && f < 16777216.0f) return f;
    double d = *(const double*)p;                 // fp64
    return (float)d;
}

__global__ void yolo_zero_kernel() {
    int t = threadIdx.x;
    if (t < 3 * NCELL) g_cellsums[t] = 0.0f;
}

__global__ void __launch_bounds__(K1_THREADS)
yolo_main_kernel(const float* __restrict__ outp,
                 const float* __restrict__ tgtp,
                 const void* wp, const void* hp)
{
    const float W = decode_dim(wp);
    const float H = decode_dim(hp);
    const float cw = W * (1.0f / SDIM);
    const float ch = H * (1.0f / SDIM);

    const int tid = threadIdx.x;
    const int i0  = blockIdx.x * K1_THREADS + tid;
    const int cell = i0 % NCELL;          // invariant across grid-stride iterations
    const float jx = (float)(cell % SDIM);
    const float iy = (float)(cell / SDIM);

    float a_xw = 0.0f, a_cm = 0.0f, a_cls = 0.0f;

    for (int i = i0; i < NPAIR; i += K1_STRIDE) {
        const float2* o2 = (const float2*)(outp + (size_t)i * DSTRIDE);
        const float2* t2 = (const float2*)(tgtp + (size_t)i * DSTRIDE);

        float o[DSTRIDE], t[DSTRIDE];
        #pragma unroll
        for (int k = 0; k < DSTRIDE / 2; k++) {
            float2 vo = __ldg(o2 + k);
            float2 vt = __ldg(t2 + k);
            o[2 * k] = vo.x; o[2 * k + 1] = vo.y;
            t[2 * k] = vt.x; t[2 * k + 1] = vt.y;
        }

        // target box
        const float tx = t[0], ty = t[1];
        const float tw = t[2] * W, th = t[3] * H;
        const float has = t[4];
        const float tcx = (jx + tx) * cw, tcy = (iy + ty) * ch;
        const float tx0 = tcx - 0.5f * tw, tx1 = tcx + 0.5f * tw;
        const float ty0 = tcy - 0.5f * th, ty1 = tcy + 0.5f * th;
        const float t_area = (tx1 - tx0) * (ty1 - ty0);

        // IOU for both predictors (conf index == height index, per reference)
        float iou[2];
        #pragma unroll
        for (int p = 0; p < 2; p++) {
            const float px = o[5 * p], py = o[5 * p + 1];
            const float pw = o[5 * p + 3] * W, ph = o[5 * p + 4] * H;
            const float pcx = (jx + px) * cw, pcy = (iy + py) * ch;
            const float px0 = pcx - 0.5f * pw, px1 = pcx + 0.5f * pw;
            const float py0 = pcy - 0.5f * ph, py1 = pcy + 0.5f * ph;
            const float iw = fmaxf(fminf(px1, tx1) - fmaxf(px0, tx0), 0.0f);
            const float ih = fmaxf(fminf(py1, ty1) - fmaxf(py0, ty0), 0.0f);
            const float inter = iw * ih;
            const float p_area = (px1 - px0) * (py1 - py0);
            iou[p] = inter / (p_area + t_area - inter + 1e-9f);
        }
        // argmax tie-break: last index among ties wins (>=)
        const float bc = (iou[1] >= iou[0]) ? o[9] : o[4];

        // last-predictor (L = P-1 = 1) losses
        const float dx = tx - o[5];
        const float dy = ty - o[6];
        const float dw = sqrtf(tw) - sqrtf(o[8] * W);
        const float dh = sqrtf(th) - sqrtf(o[9] * H);
        const float dc = has - o[9];

        a_xw += dx * dx + dy * dy + dw * dw + dh * dh;
        a_cm += dc * dc;

        float ec = 0.0f;
        #pragma unroll
        for (int c = 0; c < NCLASS; c++) {
            const float d = t[10 + c] - o[10 + c] * bc;
            ec += d * d;
        }
        a_cls += ec;

        g_has[i] = has;
    }

    // Block reduction keyed on the thread's ACTUAL cell (cell depends on
    // blockIdx, so a tid%49-indexed transpose is wrong). Consecutive tids
    // map to consecutive cells mod 49 and 32 < 49, so warp-level smem
    // atomics hit distinct addresses -> conflict-free.
    __shared__ float sc[3 * NCELL];
    if (tid < 3 * NCELL) sc[tid] = 0.0f;
    __syncthreads();
    atomicAdd(&sc[cell],             a_xw);
    atomicAdd(&sc[NCELL + cell],     a_cm);
    atomicAdd(&sc[2 * NCELL + cell], a_cls);
    __syncthreads();
    if (tid < 3 * NCELL)
        atomicAdd(&g_cellsums[tid], sc[tid]);
}

__global__ void __launch_bounds__(256)
yolo_final_kernel(float* __restrict__ loss)
{
    __shared__ float sA[NCELL], sK[NCELL];
    const int tid = threadIdx.x;
    if (tid < NCELL) {
        const float xw  = g_cellsums[tid];
        const float cm  = g_cellsums[NCELL + tid];
        const float cls = g_cellsums[2 * NCELL + tid];
        sA[tid] = 5.0f * xw + 0.5f * cm;   // coefficient of has
        sK[tid] = 0.5f * cm + cls;         // constant per cell
    }
    __syncthreads();

    const int b = blockIdx.x * 256 + tid;
    if (b < BATCH) {
        const float* hp = g_has + (size_t)b * NCELL;
        float acc = 0.0f;
        #pragma unroll
        for (int c = 0; c < NCELL; c++)
            acc += hp[c] * sA[c] + sK[c];
        loss[b] = acc;
    }
}

extern "C" void kernel_launch(void* const* d_in, const int* in_sizes, int n_in,
                              void* d_out, int out_size)
{
    const float* o = (const float*)d_in[0];
    const float* t = (const float*)d_in[1];
    const void*  wp = (n_in > 2) ? d_in[2] : nullptr;
    const void*  hp = (n_in > 3) ? d_in[3] : nullptr;

    yolo_zero_kernel<<<1, 192>>>();
    yolo_main_kernel<<<K1_BLOCKS, K1_THREADS>>>(o, t, wp, hp);
    yolo_final_kernel<<<(BATCH + 255) / 256, 256>>>((float*)d_out);
}

// round 6
// speedup vs baseline: 1.1852x; 1.1852x over previous
#include <cuda_runtime.h>

#define SDIM    7
#define NCELL   49
#define BATCH   16384
#define DSTRIDE 30
#define NPAIR   (BATCH * NCELL)          // 802816
#define NCLASS  20

#define TILE        256                  // pairs per tile
#define NTILES      (NPAIR / TILE)       // 3136 (exact)
#define K1_BLOCKS   147                  // 3*49: tile stride 147*256 ≡ 0 mod 49
#define K1_THREADS  256
#define STAGES      3
#define TILE_WORDS  (TILE * DSTRIDE)     // 7680 floats per tensor per tile
#define STAGE_WORDS (2 * TILE_WORDS)     // 15360 (out + tgt)
#define SMEM_BYTES  (STAGES * STAGE_WORDS * 4)   // 184320 B
#define CHUNKS_PER_TENSOR (TILE_WORDS * 4 / 16)  // 1920 x 16B

__device__ float    g_has[NPAIR];          // 3.2 MB
__device__ float    g_cellsums[3 * NCELL]; // XW | CM | CLS (zero-init, reset by last block)
__device__ float    g_coef[2 * NCELL];     // A (has coefficient) | K (constant)
__device__ unsigned g_ticket;              // zero-init, reset by last block

__device__ __forceinline__ float decode_dim(const void* p) {
    if (p == nullptr) return 448.0f;
    int v = *(const int*)p;
    if (v > 0 && v < (1 << 24)) return (float)v;
    float f = __int_as_float(v);
    if (f > 0.0f && f < 16777216.0f) return f;
    double d = *(const double*)p;
    return (float)d;
}

__device__ __forceinline__ void cp_async16(unsigned saddr, const void* gptr) {
    asm volatile("cp.async.cg.shared.global [%0], [%1], 16;" :: "r"(saddr), "l"(gptr));
}
__device__ __forceinline__ void cp_commit() {
    asm volatile("cp.async.commit_group;");
}
template <int N> __device__ __forceinline__ void cp_wait() {
    asm volatile("cp.async.wait_group %0;" :: "n"(N));
}

// Issue the coalesced cp.async copies for one tile into one stage.
__device__ __forceinline__ void load_tile(float* stage, int tile,
                                          const char* obase0, const char* tbase0,
                                          int tid) {
    const char* obase = obase0 + (size_t)tile * (TILE * DSTRIDE * 4);
    const char* tbase = tbase0 + (size_t)tile * (TILE * DSTRIDE * 4);
    unsigned so = (unsigned)__cvta_generic_to_shared(stage);
    unsigned st = (unsigned)__cvta_generic_to_shared(stage + TILE_WORDS);
    #pragma unroll
    for (int k = 0; k < 15; k++) {                 // 3840 chunks / 256 threads
        int c = k * K1_THREADS + tid;
        if (c < CHUNKS_PER_TENSOR)
            cp_async16(so + c * 16, obase + (size_t)c * 16);
        else {
            int c2 = c - CHUNKS_PER_TENSOR;
            cp_async16(st + c2 * 16, tbase + (size_t)c2 * 16);
        }
    }
}

__global__ void __launch_bounds__(K1_THREADS)
yolo_main_kernel(const float* __restrict__ outp,
                 const float* __restrict__ tgtp,
                 const void* wp, const void* hp)
{
    extern __shared__ float smem[];
    __shared__ float sc[3 * NCELL];
    __shared__ float s_rd[3 * NCELL];
    __shared__ unsigned s_rank;

    const float W = decode_dim(wp);
    const float H = decode_dim(hp);
    const float cw = W * (1.0f / SDIM);
    const float ch = H * (1.0f / SDIM);

    const int tid = threadIdx.x;
    // pair index = tile*256 + tid, tile advances by 147; 147*256 ≡ 0 (mod 49)
    const int cell = (blockIdx.x * K1_THREADS + tid) % NCELL;   // loop-invariant
    const float jx = (float)(cell % SDIM);
    const float iy = (float)(cell / SDIM);

    const char* ob = (const char*)outp;
    const char* tb = (const char*)tgtp;

    // ---- pipeline prologue (every block has >= 21 tiles >= STAGES) ----
    #pragma unroll
    for (int s = 0; s < STAGES; s++) {
        load_tile(smem + s * STAGE_WORDS, blockIdx.x + s * K1_BLOCKS, ob, tb, tid);
        cp_commit();
    }

    float a_xw = 0.0f, a_cm = 0.0f, a_cls = 0.0f;
    int stage = 0;

    for (int j = blockIdx.x; j < NTILES; j += K1_BLOCKS) {
        cp_wait<STAGES - 1>();
        __syncthreads();

        const float2* o2 = (const float2*)(smem + stage * STAGE_WORDS + tid * DSTRIDE);
        const float2* t2 = (const float2*)(smem + stage * STAGE_WORDS + TILE_WORDS + tid * DSTRIDE);

        float o[DSTRIDE], t[DSTRIDE];
        #pragma unroll
        for (int k = 0; k < DSTRIDE / 2; k++) {
            float2 vo = o2[k];
            float2 vt = t2[k];
            o[2 * k] = vo.x; o[2 * k + 1] = vo.y;
            t[2 * k] = vt.x; t[2 * k + 1] = vt.y;
        }

        // target box
        const float tx = t[0], ty = t[1];
        const float tw = t[2] * W, th = t[3] * H;
        const float has = t[4];
        const float tcx = (jx + tx) * cw, tcy = (iy + ty) * ch;
        const float tx0 = tcx - 0.5f * tw, tx1 = tcx + 0.5f * tw;
        const float ty0 = tcy - 0.5f * th, ty1 = tcy + 0.5f * th;
        const float t_area = (tx1 - tx0) * (ty1 - ty0);

        // IOU for both predictors (conf index == height index, per reference)
        float iou[2];
        #pragma unroll
        for (int p = 0; p < 2; p++) {
            const float px = o[5 * p], py = o[5 * p + 1];
            const float pw = o[5 * p + 3] * W, ph = o[5 * p + 4] * H;
            const float pcx = (jx + px) * cw, pcy = (iy + py) * ch;
            const float px0 = pcx - 0.5f * pw, px1 = pcx + 0.5f * pw;
            const float py0 = pcy - 0.5f * ph, py1 = pcy + 0.5f * ph;
            const float iw = fmaxf(fminf(px1, tx1) - fmaxf(px0, tx0), 0.0f);
            const float ih = fmaxf(fminf(py1, ty1) - fmaxf(py0, ty0), 0.0f);
            const float inter = iw * ih;
            const float p_area = (px1 - px0) * (py1 - py0);
            iou[p] = inter / (p_area + t_area - inter + 1e-9f);
        }
        const float bc = (iou[1] >= iou[0]) ? o[9] : o[4];   // last-index tie-break

        const float dx = tx - o[5];
        const float dy = ty - o[6];
        const float dw = sqrtf(tw) - sqrtf(o[8] * W);
        const float dh = sqrtf(th) - sqrtf(o[9] * H);
        const float dc = has - o[9];

        a_xw += dx * dx + dy * dy + dw * dw + dh * dh;
        a_cm += dc * dc;

        float ec = 0.0f;
        #pragma unroll
        for (int c = 0; c < NCLASS; c++) {
            const float d = t[10 + c] - o[10 + c] * bc;
            ec += d * d;
        }
        a_cls += ec;

        g_has[(size_t)j * TILE + tid] = has;   // coalesced STG.32

        __syncthreads();   // everyone done reading this stage

        // refill this stage with tile j + STAGES*stride
        int jn = j + STAGES * K1_BLOCKS;
        if (jn < NTILES)
            load_tile(smem + stage * STAGE_WORDS, jn, ob, tb, tid);
        cp_commit();       // commit (possibly empty) group to keep counts aligned

        stage = (stage == STAGES - 1) ? 0 : stage + 1;
    }

    // ---- one-time block reduction (cell-keyed; 32 < 49 -> conflict-free) ----
    if (tid < 3 * NCELL) sc[tid] = 0.0f;
    __syncthreads();
    atomicAdd(&sc[cell],             a_xw);
    atomicAdd(&sc[NCELL + cell],     a_cm);
    atomicAdd(&sc[2 * NCELL + cell], a_cls);
    __syncthreads();
    if (tid < 3 * NCELL)
        atomicAdd(&g_cellsums[tid], sc[tid]);

    // ---- last block computes coefficients and resets state for replay ----
    __threadfence();
    if (tid == 0) s_rank = atomicAdd(&g_ticket, 1u);
    __syncthreads();
    if (s_rank == K1_BLOCKS - 1) {
        __threadfence();
        if (tid < 3 * NCELL) s_rd[tid] = g_cellsums[tid];
        __syncthreads();
        if (tid < NCELL) {
            const float xw  = s_rd[tid];
            const float cm  = s_rd[NCELL + tid];
            const float cls = s_rd[2 * NCELL + tid];
            g_coef[tid]         = 5.0f * xw + 0.5f * cm;   // A: coefficient of has
            g_coef[NCELL + tid] = 0.5f * cm + cls;         // K: constant per cell
        }
        if (tid < 3 * NCELL) g_cellsums[tid] = 0.0f;       // reset for next replay
        if (tid == 0) g_ticket = 0u;
        __threadfence();
    }
}

__global__ void __launch_bounds__(256)
yolo_final_kernel(float* __restrict__ loss)
{
    __shared__ float sA[NCELL], sK[NCELL];
    const int tid = threadIdx.x;
    if (tid < NCELL) {
        sA[tid] = g_coef[tid];
        sK[tid] = g_coef[NCELL + tid];
    }
    __syncthreads();

    const int b = blockIdx.x * 256 + tid;
    if (b < BATCH) {
        const float* hp = g_has + (size_t)b * NCELL;
        float acc = 0.0f;
        #pragma unroll
        for (int c = 0; c < NCELL; c++)
            acc += hp[c] * sA[c] + sK[c];
        loss[b] = acc;
    }
}

extern "C" void kernel_launch(void* const* d_in, const int* in_sizes, int n_in,
                              void* d_out, int out_size)
{
    const float* o  = (const float*)d_in[0];
    const float* t  = (const float*)d_in[1];
    const void*  wp = (n_in > 2) ? d_in[2] : nullptr;
    const void*  hp = (n_in > 3) ? d_in[3] : nullptr;

    cudaFuncSetAttribute(yolo_main_kernel,
                         cudaFuncAttributeMaxDynamicSharedMemorySize, SMEM_BYTES);

    yolo_main_kernel<<<K1_BLOCKS, K1_THREADS, SMEM_BYTES>>>(o, t, wp, hp);
    yolo_final_kernel<<<(BATCH + 255) / 256, 256>>>((float*)d_out);
}

// round 9
// speedup vs baseline: 1.2435x; 1.0491x over previous
#include <cuda_runtime.h>

#define SDIM    7
#define NCELL   49
#define BATCH   16384
#define DSTRIDE 30
#define NPAIR   (BATCH * NCELL)          // 802816
#define NCLASS  20

#define TILE        256                  // pairs per tile
#define NTILES      (NPAIR / TILE)       // 3136 (exact)
#define K1_BLOCKS   147                  // 3*49: tile stride 147*256 ≡ 0 mod 49
#define K1_THREADS  256
#define STAGES      3
#define TILE_WORDS  (TILE * DSTRIDE)     // 7680 floats per tensor per tile
#define STAGE_WORDS (2 * TILE_WORDS)     // 15360 (out + tgt)
#define SMEM_BYTES  (STAGES * STAGE_WORDS * 4)   // 184320 B
#define CHUNKS_PER_TENSOR (TILE_WORDS * 4 / 16)  // 1920 x 16B

__device__ float    g_has[NPAIR];          // 3.2 MB
__device__ float    g_cellsums[3 * NCELL]; // XW | CM | CLS (zero-init, reset by last block)
__device__ float    g_coef[2 * NCELL];     // A (has coefficient) | K (constant)
__device__ unsigned g_ticket;              // zero-init, reset by last block

__device__ __forceinline__ float decode_dim(const void* p) {
    if (p == nullptr) return 448.0f;
    int v = *(const int*)p;
    if (v > 0 && v < (1 << 24)) return (float)v;
    float f = __int_as_float(v);
    if (f > 0.0f && f < 16777216.0f) return f;
    double d = *(const double*)p;
    return (float)d;
}

__device__ __forceinline__ void cp_async16(unsigned saddr, const void* gptr) {
    asm volatile("cp.async.cg.shared.global [%0], [%1], 16;" :: "r"(saddr), "l"(gptr));
}
__device__ __forceinline__ void cp_commit() {
    asm volatile("cp.async.commit_group;");
}
template <int N> __device__ __forceinline__ void cp_wait() {
    asm volatile("cp.async.wait_group %0;" :: "n"(N));
}

// Issue the coalesced cp.async copies for one tile into one stage.
__device__ __forceinline__ void load_tile(float* stage, int tile,
                                          const char* obase0, const char* tbase0,
                                          int tid) {
    const char* obase = obase0 + (size_t)tile * (TILE * DSTRIDE * 4);
    const char* tbase = tbase0 + (size_t)tile * (TILE * DSTRIDE * 4);
    unsigned so = (unsigned)__cvta_generic_to_shared(stage);
    unsigned st = (unsigned)__cvta_generic_to_shared(stage + TILE_WORDS);
    #pragma unroll
    for (int k = 0; k < 15; k++) {                 // 3840 chunks / 256 threads
        int c = k * K1_THREADS + tid;
        if (c < CHUNKS_PER_TENSOR)
            cp_async16(so + c * 16, obase + (size_t)c * 16);
        else {
            int c2 = c - CHUNKS_PER_TENSOR;
            cp_async16(st + c2 * 16, tbase + (size_t)c2 * 16);
        }
    }
}

__global__ void __launch_bounds__(K1_THREADS)
yolo_main_kernel(const float* __restrict__ outp,
                 const float* __restrict__ tgtp,
                 const void* wp, const void* hp)
{
    extern __shared__ float smem[];
    __shared__ float sc[3 * NCELL];
    __shared__ float s_rd[3 * NCELL];
    __shared__ unsigned s_rank;

    const float W = decode_dim(wp);
    const float H = decode_dim(hp);
    const float cw = W * (1.0f / SDIM);
    const float ch = H * (1.0f / SDIM);

    const int tid = threadIdx.x;
    // pair index = tile*256 + tid, tile advances by 147; 147*256 ≡ 0 (mod 49)
    const int cell = (blockIdx.x * K1_THREADS + tid) % NCELL;   // loop-invariant
    const float jx = (float)(cell % SDIM);
    const float iy = (float)(cell / SDIM);

    const char* ob = (const char*)outp;
    const char* tb = (const char*)tgtp;

    // ---- pipeline prologue (every block has >= 21 tiles >= STAGES) ----
    #pragma unroll
    for (int s = 0; s < STAGES; s++) {
        load_tile(smem + s * STAGE_WORDS, blockIdx.x + s * K1_BLOCKS, ob, tb, tid);
        cp_commit();
    }

    float a_xw = 0.0f, a_cm = 0.0f, a_cls = 0.0f;
    int stage = 0;

    for (int j = blockIdx.x; j < NTILES; j += K1_BLOCKS) {
        cp_wait<STAGES - 1>();
        __syncthreads();

        const float2* o2 = (const float2*)(smem + stage * STAGE_WORDS + tid * DSTRIDE);
        const float2* t2 = (const float2*)(smem + stage * STAGE_WORDS + TILE_WORDS + tid * DSTRIDE);

        float o[DSTRIDE], t[DSTRIDE];
        #pragma unroll
        for (int k = 0; k < DSTRIDE / 2; k++) {
            float2 vo = o2[k];
            float2 vt = t2[k];
            o[2 * k] = vo.x; o[2 * k + 1] = vo.y;
            t[2 * k] = vt.x; t[2 * k + 1] = vt.y;
        }

        // target box
        const float tx = t[0], ty = t[1];
        const float tw = t[2] * W, th = t[3] * H;
        const float has = t[4];
        const float tcx = (jx + tx) * cw, tcy = (iy + ty) * ch;
        const float tx0 = tcx - 0.5f * tw, tx1 = tcx + 0.5f * tw;
        const float ty0 = tcy - 0.5f * th, ty1 = tcy + 0.5f * th;
        const float t_area = (tx1 - tx0) * (ty1 - ty0);

        // IOU for both predictors (conf index == height index, per reference)
        float iou[2];
        #pragma unroll
        for (int p = 0; p < 2; p++) {
            const float px = o[5 * p], py = o[5 * p + 1];
            const float pw = o[5 * p + 3] * W, ph = o[5 * p + 4] * H;
            const float pcx = (jx + px) * cw, pcy = (iy + py) * ch;
            const float px0 = pcx - 0.5f * pw, px1 = pcx + 0.5f * pw;
            const float py0 = pcy - 0.5f * ph, py1 = pcy + 0.5f * ph;
            const float iw = fmaxf(fminf(px1, tx1) - fmaxf(px0, tx0), 0.0f);
            const float ih = fmaxf(fminf(py1, ty1) - fmaxf(py0, ty0), 0.0f);
            const float inter = iw * ih;
            const float p_area = (px1 - px0) * (py1 - py0);
            iou[p] = inter / (p_area + t_area - inter + 1e-9f);
        }
        const float bc = (iou[1] >= iou[0]) ? o[9] : o[4];   // last-index tie-break

        const float dx = tx - o[5];
        const float dy = ty - o[6];
        const float dw = sqrtf(tw) - sqrtf(o[8] * W);
        const float dh = sqrtf(th) - sqrtf(o[9] * H);
        const float dc = has - o[9];

        a_xw += dx * dx + dy * dy + dw * dw + dh * dh;
        a_cm += dc * dc;

        float ec = 0.0f;
        #pragma unroll
        for (int c = 0; c < NCLASS; c++) {
            const float d = t[10 + c] - o[10 + c] * bc;
            ec += d * d;
        }
        a_cls += ec;

        g_has[(size_t)j * TILE + tid] = has;   // coalesced STG.32

        __syncthreads();   // everyone done reading this stage

        // refill this stage with tile j + STAGES*stride
        int jn = j + STAGES * K1_BLOCKS;
        if (jn < NTILES)
            load_tile(smem + stage * STAGE_WORDS, jn, ob, tb, tid);
        cp_commit();       // commit (possibly empty) group to keep counts aligned

        stage = (stage == STAGES - 1) ? 0 : stage + 1;
    }

    // ---- one-time block reduction (cell-keyed; 32 < 49 -> conflict-free) ----
    if (tid < 3 * NCELL) sc[tid] = 0.0f;
    __syncthreads();
    atomicAdd(&sc[cell],             a_xw);
    atomicAdd(&sc[NCELL + cell],     a_cm);
    atomicAdd(&sc[2 * NCELL + cell], a_cls);
    __syncthreads();
    if (tid < 3 * NCELL)
        atomicAdd(&g_cellsums[tid], sc[tid]);

    // ---- last block computes coefficients and resets state for replay ----
    __threadfence();
    if (tid == 0) s_rank = atomicAdd(&g_ticket, 1u);
    __syncthreads();
    if (s_rank == K1_BLOCKS - 1) {
        __threadfence();
        if (tid < 3 * NCELL) s_rd[tid] = g_cellsums[tid];
        __syncthreads();
        if (tid < NCELL) {
            const float xw  = s_rd[tid];
            const float cm  = s_rd[NCELL + tid];
            const float cls = s_rd[2 * NCELL + tid];
            g_coef[tid]         = 5.0f * xw + 0.5f * cm;   // A: coefficient of has
            g_coef[NCELL + tid] = 0.5f * cm + cls;         // K: constant per cell
        }
        if (tid < 3 * NCELL) g_cellsums[tid] = 0.0f;       // reset for next replay
        if (tid == 0) g_ticket = 0u;
        __threadfence();
    }
}

// One warp per batch row: lane l covers cells l and l+32, then SHFL reduce.
// 16384 warps -> 2048 blocks of 256 threads: full-chip parallelism instead of
// the previous 64-block latency-bound loop (7.36us, occ 11.7%).
__global__ void __launch_bounds__(256)
yolo_final_kernel(float* __restrict__ loss)
{
    const int lane = threadIdx.x & 31;
    const int b = (blockIdx.x * 256 + threadIdx.x) >> 5;   // global warp id

    const float* hp = g_has + (size_t)b * NCELL;

    float v = __ldg(hp + lane) * __ldg(g_coef + lane) + __ldg(g_coef + NCELL + lane);
    if (lane < NCELL - 32) {
        v += __ldg(hp + lane + 32) * __ldg(g_coef + lane + 32)
           + __ldg(g_coef + NCELL + lane + 32);
    }

    #pragma unroll
    for (int s = 16; s > 0; s >>= 1)
        v += __shfl_xor_sync(0xFFFFFFFFu, v, s);

    if (lane == 0)
        loss[b] = v;
}

extern "C" void kernel_launch(void* const* d_in, const int* in_sizes, int n_in,
                              void* d_out, int out_size)
{
    const float* o  = (const float*)d_in[0];
    const float* t  = (const float*)d_in[1];
    const void*  wp = (n_in > 2) ? d_in[2] : nullptr;
    const void*  hp = (n_in > 3) ? d_in[3] : nullptr;

    cudaFuncSetAttribute(yolo_main_kernel,
                         cudaFuncAttributeMaxDynamicSharedMemorySize, SMEM_BYTES);

    yolo_main_kernel<<<K1_BLOCKS, K1_THREADS, SMEM_BYTES>>>(o, t, wp, hp);
    yolo_final_kernel<<<BATCH / 8, 256>>>((float*)d_out);   // 2048 blocks, 8 warps each
}